// round 2
// baseline (speedup 1.0000x reference)
#include <cuda_runtime.h>
#include <cstdint>

#define W_  256
#define H_  256
#define C_  256
#define HW_ (H_*W_)
#define N_  1024
#define B_  4
#define BN  (B_*N_)

typedef unsigned long long ull;

// ---- packed f32x2 helpers (Blackwell sm_100+) ----
__device__ __forceinline__ ull pack2(float a) {
    ull r; unsigned ai = __float_as_uint(a);
    asm("mov.b64 %0, {%1,%1};" : "=l"(r) : "r"(ai));
    return r;
}
__device__ __forceinline__ void fma2(ull& d, ull a, ull b) {
    asm("fma.rn.f32x2 %0, %1, %2, %0;" : "+l"(d) : "l"(a), "l"(b));
}
__device__ __forceinline__ float2 unpack2(ull v) {
    unsigned lo, hi;
    asm("mov.b64 {%0,%1}, %2;" : "=r"(lo), "=r"(hi) : "l"(v));
    return make_float2(__uint_as_float(lo), __uint_as_float(hi));
}

// scratch: pooled features [BN][128]
__device__ float g_pooled[BN * 128];

// ============================================================================
// Kernel 1: per-vertex ROI-align + Wc GEMM + ReLU + mean-pool
// One block per vertex. 128 threads.  (smem = 17,920 B, occupancy 4)
// ============================================================================
__global__ __launch_bounds__(128, 4)
void roi_pool_kernel(const float* __restrict__ features,
                     const float* __restrict__ vertices,
                     const float* __restrict__ Wc,
                     const float* __restrict__ bc)
{
    __shared__ __align__(16) float sF8[16][64];    // 16 channels x 8x8 pixels
    __shared__ __align__(16) float sR2[16][56];    // bilinear values, padded
    __shared__ __align__(16) float sWc[16][128];   // Wc tile, o-contiguous
    __shared__ float sRed[4][128];

    const int tid = threadIdx.x;
    const int bid = blockIdx.x;          // b*N + n
    const int b = bid >> 10;

    const float vx = vertices[bid * 2 + 0];
    const float vy = vertices[bid * 2 + 1];
    // start = v - 4; sample_i = start + 0.5 + i = (v - 3.5) + i
    const float fx = vx - 3.5f, fy = vy - 3.5f;
    int ix = (int)floorf(fx), iy = (int)floorf(fy);
    const float lx = fx - (float)ix, ly = fy - (float)iy;
    ix = max(0, min(ix, W_ - 8));
    iy = max(0, min(iy, H_ - 8));
    const float hx = 1.f - lx, hy = 1.f - ly;
    const float w00 = hy * hx, w01 = hy * lx, w10 = ly * hx, w11 = ly * lx;

    // per-thread gather pointer: pixel p = tid&63 (row p>>3, col p&7),
    // channel offset hi = tid>>6; iteration j covers channel hi + 2j.
    const float* gp = features + (size_t)b * C_ * HW_
                    + (size_t)(iy + ((tid & 63) >> 3)) * W_ + (ix + (tid & 7))
                    + (size_t)(tid >> 6) * HW_;

    // zero the R padding once (never overwritten afterwards)
    if (tid < 16 * 7) sR2[tid / 7][49 + tid % 7] = 0.f;

    const int to  = tid & 31;   // lane  -> 4 output channels to*4..to*4+3
    const int thw = tid >> 5;   // warp  -> 7 hw-pairs thw*7..thw*7+6

    ull acc[4][7];
    #pragma unroll
    for (int i = 0; i < 4; i++)
        #pragma unroll
        for (int j = 0; j < 7; j++) acc[i][j] = 0ULL;

    float pf[8];
    #pragma unroll
    for (int j = 0; j < 8; j++) pf[j] = __ldg(gp + (size_t)(2 * j) * HW_);

    for (int t = 0; t < 16; ++t) {
        const int c0 = t * 16;
        __syncthreads();                      // prior FFMA phase done
        {   // commit prefetched feature tile to smem
            const int hi = tid >> 6, p = tid & 63;
            #pragma unroll
            for (int j = 0; j < 8; j++) sF8[hi + 2 * j][p] = pf[j];
        }
        // stage Wc tile
        #pragma unroll
        for (int e = 0; e < 16; ++e) {
            const int idx = e * 128 + tid;
            const int c_l = idx & 15, o = idx >> 4;
            sWc[c_l][o] = __ldg(&Wc[o * 256 + c0 + c_l]);
        }
        __syncthreads();
        // bilinear combine -> R
        for (int e = tid; e < 16 * 49; e += 128) {
            const int c_l = e / 49;
            const int hw  = e - c_l * 49;
            const int py  = hw / 7;
            const int px  = hw - py * 7;
            const float* F = &sF8[c_l][py * 8 + px];
            sR2[c_l][hw] = w00 * F[0] + w01 * F[1] + w10 * F[8] + w11 * F[9];
        }
        // prefetch next feature tile (latency hidden under FFMA phase)
        if (t < 15) {
            const float* gp2 = gp + (size_t)(t + 1) * 16 * HW_;
            #pragma unroll
            for (int j = 0; j < 8; j++) pf[j] = __ldg(gp2 + (size_t)(2 * j) * HW_);
        }
        __syncthreads();
        // FFMA2 GEMM over this 16-channel tile
        #pragma unroll
        for (int c = 0; c < 16; ++c) {
            const float4 wv = *(const float4*)&sWc[c][to * 4];
            const ull w0 = pack2(wv.x), w1 = pack2(wv.y);
            const ull w2 = pack2(wv.z), w3 = pack2(wv.w);
            const ull* Rrow = (const ull*)&sR2[c][0];   // broadcast reads
            #pragma unroll
            for (int j = 0; j < 7; j++) {
                const ull r = Rrow[thw * 7 + j];
                fma2(acc[0][j], w0, r);
                fma2(acc[1][j], w1, r);
                fma2(acc[2][j], w2, r);
                fma2(acc[3][j], w3, r);
            }
        }
    }

    // epilogue: bias + relu + partial sum over this thread's 14 hw slots
    float part[4] = {0.f, 0.f, 0.f, 0.f};
    #pragma unroll
    for (int oi = 0; oi < 4; ++oi) {
        const float bias = __ldg(&bc[to * 4 + oi]);
        #pragma unroll
        for (int j = 0; j < 7; j++) {
            const float2 v = unpack2(acc[oi][j]);
            const int hw0 = 2 * (thw * 7 + j);
            if (hw0     < 49) part[oi] += fmaxf(v.x + bias, 0.f);
            if (hw0 + 1 < 49) part[oi] += fmaxf(v.y + bias, 0.f);
        }
    }
    #pragma unroll
    for (int oi = 0; oi < 4; ++oi) sRed[thw][to * 4 + oi] = part[oi];
    __syncthreads();
    if (tid < 128) {
        const float s = sRed[0][tid] + sRed[1][tid] + sRed[2][tid] + sRed[3][tid];
        g_pooled[bid * 128 + tid] = s * (1.0f / 49.0f);
    }
}

// ============================================================================
// Kernel 2: MLP + heads.  16 vertices per block, 256 threads.
// Weights read directly from L2 (contiguous per-thread rows, float4).
// smem = 40,960 B < 48 KB static limit.
// ============================================================================
__global__ __launch_bounds__(256)
void mlp_kernel(const float* __restrict__ W1, const float* __restrict__ b1,
                const float* __restrict__ W2, const float* __restrict__ b2,
                const float* __restrict__ Wa, const float* __restrict__ ba,
                const float* __restrict__ Wr, const float* __restrict__ br,
                const float* __restrict__ Ww, const float* __restrict__ bw,
                float* __restrict__ out)
{
    __shared__ __align__(16) float pT[128][20];    // pooled, transposed (k-major)
    __shared__ __align__(16) float h1T[256][20];
    __shared__ __align__(16) float h2T[128][20];

    const int tid  = threadIdx.x;
    const int base = blockIdx.x * 16;

    for (int e = tid; e < 16 * 128; e += 256) {
        const int v = e >> 7, k = e & 127;
        pT[k][v] = g_pooled[(base + v) * 128 + k];
    }
    __syncthreads();

    // ---- h1 = relu(pooled @ W1^T + b1): thread = output channel (256) ----
    float acc[16];
    #pragma unroll
    for (int v = 0; v < 16; v++) acc[v] = 0.f;
    {
        const float4* w1row = (const float4*)(W1 + tid * 128);
        #pragma unroll 4
        for (int k4 = 0; k4 < 32; ++k4) {
            const float4 w4 = __ldg(&w1row[k4]);
            const float wk[4] = {w4.x, w4.y, w4.z, w4.w};
            #pragma unroll
            for (int u = 0; u < 4; ++u) {
                const float w = wk[u];
                const float4* pr = (const float4*)pT[k4 * 4 + u];  // broadcast
                const float4 a0 = pr[0], a1 = pr[1], a2 = pr[2], a3 = pr[3];
                acc[0]  = fmaf(w, a0.x, acc[0]);  acc[1]  = fmaf(w, a0.y, acc[1]);
                acc[2]  = fmaf(w, a0.z, acc[2]);  acc[3]  = fmaf(w, a0.w, acc[3]);
                acc[4]  = fmaf(w, a1.x, acc[4]);  acc[5]  = fmaf(w, a1.y, acc[5]);
                acc[6]  = fmaf(w, a1.z, acc[6]);  acc[7]  = fmaf(w, a1.w, acc[7]);
                acc[8]  = fmaf(w, a2.x, acc[8]);  acc[9]  = fmaf(w, a2.y, acc[9]);
                acc[10] = fmaf(w, a2.z, acc[10]); acc[11] = fmaf(w, a2.w, acc[11]);
                acc[12] = fmaf(w, a3.x, acc[12]); acc[13] = fmaf(w, a3.y, acc[13]);
                acc[14] = fmaf(w, a3.z, acc[14]); acc[15] = fmaf(w, a3.w, acc[15]);
            }
        }
    }
    {
        const float bb = __ldg(&b1[tid]);
        #pragma unroll
        for (int v = 0; v < 16; v++) h1T[tid][v] = fmaxf(acc[v] + bb, 0.f);
    }
    __syncthreads();

    // ---- h2 = relu(h1 @ W2^T + b2): thread = (channel 128, vertex-half) ----
    const int c2 = tid & 127, vh = tid >> 7;
    float acc2[8];
    #pragma unroll
    for (int i = 0; i < 8; i++) acc2[i] = 0.f;
    {
        const float4* w2row = (const float4*)(W2 + c2 * 256);
        #pragma unroll 4
        for (int k4 = 0; k4 < 64; ++k4) {
            const float4 w4 = __ldg(&w2row[k4]);
            const float wk[4] = {w4.x, w4.y, w4.z, w4.w};
            #pragma unroll
            for (int u = 0; u < 4; ++u) {
                const float w = wk[u];
                const float4* hr = (const float4*)h1T[k4 * 4 + u];
                const float4 x0 = hr[vh * 2], x1 = hr[vh * 2 + 1];
                acc2[0] = fmaf(w, x0.x, acc2[0]); acc2[1] = fmaf(w, x0.y, acc2[1]);
                acc2[2] = fmaf(w, x0.z, acc2[2]); acc2[3] = fmaf(w, x0.w, acc2[3]);
                acc2[4] = fmaf(w, x1.x, acc2[4]); acc2[5] = fmaf(w, x1.y, acc2[5]);
                acc2[6] = fmaf(w, x1.z, acc2[6]); acc2[7] = fmaf(w, x1.w, acc2[7]);
            }
        }
    }
    {
        const float b2v = __ldg(&b2[c2]);
        #pragma unroll
        for (int i = 0; i < 8; i++) h2T[c2][vh * 8 + i] = fmaxf(acc2[i] + b2v, 0.f);
    }
    __syncthreads();

    // ---- heads: d_angle[2], d_radius[1], d_width[1] per vertex ----
    if (tid < 64) {
        const int v = tid >> 2, hd = tid & 3;
        const float* wr; float bias;
        if      (hd == 0) { wr = Wa;       bias = __ldg(&ba[0]); }
        else if (hd == 1) { wr = Wa + 128; bias = __ldg(&ba[1]); }
        else if (hd == 2) { wr = Wr;       bias = __ldg(&br[0]); }
        else              { wr = Ww;       bias = __ldg(&bw[0]); }
        float s = bias;
        #pragma unroll 4
        for (int k = 0; k < 128; k++) s = fmaf(__ldg(&wr[k]), h2T[k][v], s);
        const int g = base + v;
        if      (hd <  2) out[g * 2 + hd]   = s;   // d_angle [BN,2]
        else if (hd == 2) out[2 * BN + g]   = s;   // d_radius [BN]
        else              out[3 * BN + g]   = s;   // d_width [BN]
    }
}

// ============================================================================
extern "C" void kernel_launch(void* const* d_in, const int* in_sizes, int n_in,
                              void* d_out, int out_size)
{
    const float* features = (const float*)d_in[0];
    const float* vertices = (const float*)d_in[1];
    const float* Wc = (const float*)d_in[2];
    const float* bc = (const float*)d_in[3];
    const float* W1 = (const float*)d_in[4];
    const float* b1 = (const float*)d_in[5];
    const float* W2 = (const float*)d_in[6];
    const float* b2 = (const float*)d_in[7];
    const float* Wa = (const float*)d_in[8];
    const float* ba = (const float*)d_in[9];
    const float* Wr = (const float*)d_in[10];
    const float* br = (const float*)d_in[11];
    const float* Ww = (const float*)d_in[12];
    const float* bw = (const float*)d_in[13];
    float* out = (float*)d_out;

    roi_pool_kernel<<<BN, 128>>>(features, vertices, Wc, bc);
    mlp_kernel<<<BN / 16, 256>>>(W1, b1, W2, b2, Wa, ba, Wr, br, Ww, bw, out);
}

// round 3
// speedup vs baseline: 1.0003x; 1.0003x over previous
#include <cuda_runtime.h>
#include <cstdint>

#define W_  256
#define H_  256
#define C_  256
#define HW_ (H_*W_)
#define N_  1024
#define B_  4
#define BN  (B_*N_)

typedef unsigned long long ull;

// ---- packed f32x2 helpers (Blackwell sm_100+) ----
__device__ __forceinline__ ull pack2(float a) {
    ull r; unsigned ai = __float_as_uint(a);
    asm("mov.b64 %0, {%1,%1};" : "=l"(r) : "r"(ai));
    return r;
}
__device__ __forceinline__ void fma2(ull& d, ull a, ull b) {
    asm("fma.rn.f32x2 %0, %1, %2, %0;" : "+l"(d) : "l"(a), "l"(b));
}
__device__ __forceinline__ float2 unpack2(ull v) {
    unsigned lo, hi;
    asm("mov.b64 {%0,%1}, %2;" : "=r"(lo), "=r"(hi) : "l"(v));
    return make_float2(__uint_as_float(lo), __uint_as_float(hi));
}

// scratch: pooled features [BN][128]
__device__ float g_pooled[BN * 128];

// ============================================================================
// Kernel 1: per-vertex ROI-align + Wc GEMM + ReLU + mean-pool
// One block per vertex. 128 threads.  (smem = 17,920 B, occupancy 4)
// ============================================================================
__global__ __launch_bounds__(128, 4)
void roi_pool_kernel(const float* __restrict__ features,
                     const float* __restrict__ vertices,
                     const float* __restrict__ Wc,
                     const float* __restrict__ bc)
{
    __shared__ __align__(16) float sF8[16][64];    // 16 channels x 8x8 pixels
    __shared__ __align__(16) float sR2[16][56];    // bilinear values, padded
    __shared__ __align__(16) float sWc[16][128];   // Wc tile, o-contiguous
    __shared__ float sRed[4][128];

    const int tid = threadIdx.x;
    const int bid = blockIdx.x;          // b*N + n
    const int b = bid >> 10;

    const float vx = vertices[bid * 2 + 0];
    const float vy = vertices[bid * 2 + 1];
    // start = v - 4; sample_i = start + 0.5 + i = (v - 3.5) + i
    const float fx = vx - 3.5f, fy = vy - 3.5f;
    int ix = (int)floorf(fx), iy = (int)floorf(fy);
    const float lx = fx - (float)ix, ly = fy - (float)iy;
    ix = max(0, min(ix, W_ - 8));
    iy = max(0, min(iy, H_ - 8));
    const float hx = 1.f - lx, hy = 1.f - ly;
    const float w00 = hy * hx, w01 = hy * lx, w10 = ly * hx, w11 = ly * lx;

    // per-thread gather pointer: pixel p = tid&63 (row p>>3, col p&7),
    // channel offset hi = tid>>6; iteration j covers channel hi + 2j.
    const float* gp = features + (size_t)b * C_ * HW_
                    + (size_t)(iy + ((tid & 63) >> 3)) * W_ + (ix + (tid & 7))
                    + (size_t)(tid >> 6) * HW_;

    // zero the R padding once (never overwritten afterwards)
    if (tid < 16 * 7) sR2[tid / 7][49 + tid % 7] = 0.f;

    const int to  = tid & 31;   // lane  -> 4 output channels to*4..to*4+3
    const int thw = tid >> 5;   // warp  -> 7 hw-pairs thw*7..thw*7+6

    ull acc[4][7];
    #pragma unroll
    for (int i = 0; i < 4; i++)
        #pragma unroll
        for (int j = 0; j < 7; j++) acc[i][j] = 0ULL;

    float pf[8];
    #pragma unroll
    for (int j = 0; j < 8; j++) pf[j] = __ldg(gp + (size_t)(2 * j) * HW_);

    for (int t = 0; t < 16; ++t) {
        const int c0 = t * 16;
        __syncthreads();                      // prior FFMA phase done
        {   // commit prefetched feature tile to smem
            const int hi = tid >> 6, p = tid & 63;
            #pragma unroll
            for (int j = 0; j < 8; j++) sF8[hi + 2 * j][p] = pf[j];
        }
        // stage Wc tile
        #pragma unroll
        for (int e = 0; e < 16; ++e) {
            const int idx = e * 128 + tid;
            const int c_l = idx & 15, o = idx >> 4;
            sWc[c_l][o] = __ldg(&Wc[o * 256 + c0 + c_l]);
        }
        __syncthreads();
        // bilinear combine -> R
        for (int e = tid; e < 16 * 49; e += 128) {
            const int c_l = e / 49;
            const int hw  = e - c_l * 49;
            const int py  = hw / 7;
            const int px  = hw - py * 7;
            const float* F = &sF8[c_l][py * 8 + px];
            sR2[c_l][hw] = w00 * F[0] + w01 * F[1] + w10 * F[8] + w11 * F[9];
        }
        // prefetch next feature tile (latency hidden under FFMA phase)
        if (t < 15) {
            const float* gp2 = gp + (size_t)(t + 1) * 16 * HW_;
            #pragma unroll
            for (int j = 0; j < 8; j++) pf[j] = __ldg(gp2 + (size_t)(2 * j) * HW_);
        }
        __syncthreads();
        // FFMA2 GEMM over this 16-channel tile
        #pragma unroll
        for (int c = 0; c < 16; ++c) {
            const float4 wv = *(const float4*)&sWc[c][to * 4];
            const ull w0 = pack2(wv.x), w1 = pack2(wv.y);
            const ull w2 = pack2(wv.z), w3 = pack2(wv.w);
            const ull* Rrow = (const ull*)&sR2[c][0];   // broadcast reads
            #pragma unroll
            for (int j = 0; j < 7; j++) {
                const ull r = Rrow[thw * 7 + j];
                fma2(acc[0][j], w0, r);
                fma2(acc[1][j], w1, r);
                fma2(acc[2][j], w2, r);
                fma2(acc[3][j], w3, r);
            }
        }
    }

    // epilogue: bias + relu + partial sum over this thread's 14 hw slots
    float part[4] = {0.f, 0.f, 0.f, 0.f};
    #pragma unroll
    for (int oi = 0; oi < 4; ++oi) {
        const float bias = __ldg(&bc[to * 4 + oi]);
        #pragma unroll
        for (int j = 0; j < 7; j++) {
            const float2 v = unpack2(acc[oi][j]);
            const int hw0 = 2 * (thw * 7 + j);
            if (hw0     < 49) part[oi] += fmaxf(v.x + bias, 0.f);
            if (hw0 + 1 < 49) part[oi] += fmaxf(v.y + bias, 0.f);
        }
    }
    #pragma unroll
    for (int oi = 0; oi < 4; ++oi) sRed[thw][to * 4 + oi] = part[oi];
    __syncthreads();
    if (tid < 128) {
        const float s = sRed[0][tid] + sRed[1][tid] + sRed[2][tid] + sRed[3][tid];
        g_pooled[bid * 128 + tid] = s * (1.0f / 49.0f);
    }
}

// ============================================================================
// Kernel 2: MLP + heads.  16 vertices per block, 256 threads.
// Weights read directly from L2 (contiguous per-thread rows, float4).
// smem = 40,960 B < 48 KB static limit.
// ============================================================================
__global__ __launch_bounds__(256)
void mlp_kernel(const float* __restrict__ W1, const float* __restrict__ b1,
                const float* __restrict__ W2, const float* __restrict__ b2,
                const float* __restrict__ Wa, const float* __restrict__ ba,
                const float* __restrict__ Wr, const float* __restrict__ br,
                const float* __restrict__ Ww, const float* __restrict__ bw,
                float* __restrict__ out)
{
    __shared__ __align__(16) float pT[128][20];    // pooled, transposed (k-major)
    __shared__ __align__(16) float h1T[256][20];
    __shared__ __align__(16) float h2T[128][20];

    const int tid  = threadIdx.x;
    const int base = blockIdx.x * 16;

    for (int e = tid; e < 16 * 128; e += 256) {
        const int v = e >> 7, k = e & 127;
        pT[k][v] = g_pooled[(base + v) * 128 + k];
    }
    __syncthreads();

    // ---- h1 = relu(pooled @ W1^T + b1): thread = output channel (256) ----
    float acc[16];
    #pragma unroll
    for (int v = 0; v < 16; v++) acc[v] = 0.f;
    {
        const float4* w1row = (const float4*)(W1 + tid * 128);
        #pragma unroll 4
        for (int k4 = 0; k4 < 32; ++k4) {
            const float4 w4 = __ldg(&w1row[k4]);
            const float wk[4] = {w4.x, w4.y, w4.z, w4.w};
            #pragma unroll
            for (int u = 0; u < 4; ++u) {
                const float w = wk[u];
                const float4* pr = (const float4*)pT[k4 * 4 + u];  // broadcast
                const float4 a0 = pr[0], a1 = pr[1], a2 = pr[2], a3 = pr[3];
                acc[0]  = fmaf(w, a0.x, acc[0]);  acc[1]  = fmaf(w, a0.y, acc[1]);
                acc[2]  = fmaf(w, a0.z, acc[2]);  acc[3]  = fmaf(w, a0.w, acc[3]);
                acc[4]  = fmaf(w, a1.x, acc[4]);  acc[5]  = fmaf(w, a1.y, acc[5]);
                acc[6]  = fmaf(w, a1.z, acc[6]);  acc[7]  = fmaf(w, a1.w, acc[7]);
                acc[8]  = fmaf(w, a2.x, acc[8]);  acc[9]  = fmaf(w, a2.y, acc[9]);
                acc[10] = fmaf(w, a2.z, acc[10]); acc[11] = fmaf(w, a2.w, acc[11]);
                acc[12] = fmaf(w, a3.x, acc[12]); acc[13] = fmaf(w, a3.y, acc[13]);
                acc[14] = fmaf(w, a3.z, acc[14]); acc[15] = fmaf(w, a3.w, acc[15]);
            }
        }
    }
    {
        const float bb = __ldg(&b1[tid]);
        #pragma unroll
        for (int v = 0; v < 16; v++) h1T[tid][v] = fmaxf(acc[v] + bb, 0.f);
    }
    __syncthreads();

    // ---- h2 = relu(h1 @ W2^T + b2): thread = (channel 128, vertex-half) ----
    const int c2 = tid & 127, vh = tid >> 7;
    float acc2[8];
    #pragma unroll
    for (int i = 0; i < 8; i++) acc2[i] = 0.f;
    {
        const float4* w2row = (const float4*)(W2 + c2 * 256);
        #pragma unroll 4
        for (int k4 = 0; k4 < 64; ++k4) {
            const float4 w4 = __ldg(&w2row[k4]);
            const float wk[4] = {w4.x, w4.y, w4.z, w4.w};
            #pragma unroll
            for (int u = 0; u < 4; ++u) {
                const float w = wk[u];
                const float4* hr = (const float4*)h1T[k4 * 4 + u];
                const float4 x0 = hr[vh * 2], x1 = hr[vh * 2 + 1];
                acc2[0] = fmaf(w, x0.x, acc2[0]); acc2[1] = fmaf(w, x0.y, acc2[1]);
                acc2[2] = fmaf(w, x0.z, acc2[2]); acc2[3] = fmaf(w, x0.w, acc2[3]);
                acc2[4] = fmaf(w, x1.x, acc2[4]); acc2[5] = fmaf(w, x1.y, acc2[5]);
                acc2[6] = fmaf(w, x1.z, acc2[6]); acc2[7] = fmaf(w, x1.w, acc2[7]);
            }
        }
    }
    {
        const float b2v = __ldg(&b2[c2]);
        #pragma unroll
        for (int i = 0; i < 8; i++) h2T[c2][vh * 8 + i] = fmaxf(acc2[i] + b2v, 0.f);
    }
    __syncthreads();

    // ---- heads: d_angle[2], d_radius[1], d_width[1] per vertex ----
    if (tid < 64) {
        const int v = tid >> 2, hd = tid & 3;
        const float* wr; float bias;
        if      (hd == 0) { wr = Wa;       bias = __ldg(&ba[0]); }
        else if (hd == 1) { wr = Wa + 128; bias = __ldg(&ba[1]); }
        else if (hd == 2) { wr = Wr;       bias = __ldg(&br[0]); }
        else              { wr = Ww;       bias = __ldg(&bw[0]); }
        float s = bias;
        #pragma unroll 4
        for (int k = 0; k < 128; k++) s = fmaf(__ldg(&wr[k]), h2T[k][v], s);
        const int g = base + v;
        if      (hd <  2) out[g * 2 + hd]   = s;   // d_angle [BN,2]
        else if (hd == 2) out[2 * BN + g]   = s;   // d_radius [BN]
        else              out[3 * BN + g]   = s;   // d_width [BN]
    }
}

// ============================================================================
extern "C" void kernel_launch(void* const* d_in, const int* in_sizes, int n_in,
                              void* d_out, int out_size)
{
    const float* features = (const float*)d_in[0];
    const float* vertices = (const float*)d_in[1];
    const float* Wc = (const float*)d_in[2];
    const float* bc = (const float*)d_in[3];
    const float* W1 = (const float*)d_in[4];
    const float* b1 = (const float*)d_in[5];
    const float* W2 = (const float*)d_in[6];
    const float* b2 = (const float*)d_in[7];
    const float* Wa = (const float*)d_in[8];
    const float* ba = (const float*)d_in[9];
    const float* Wr = (const float*)d_in[10];
    const float* br = (const float*)d_in[11];
    const float* Ww = (const float*)d_in[12];
    const float* bw = (const float*)d_in[13];
    float* out = (float*)d_out;

    roi_pool_kernel<<<BN, 128>>>(features, vertices, Wc, bc);
    mlp_kernel<<<BN / 16, 256>>>(W1, b1, W2, b2, Wa, ba, Wr, br, Ww, bw, out);
}

// round 5
// speedup vs baseline: 2.4725x; 2.4717x over previous
#include <cuda_runtime.h>
#include <cstdint>

#define W_  256
#define H_  256
#define C_  256
#define HW_ 65536
#define B_  4
#define BN  4096
#define OC  128
#define NT  64
#define NTILES 4096
#define GRID_GEMM 148
#define BSTR 260                    // B smem row stride (floats)
#define AFRAG_BYTES 131072          // 32 ksteps x 8 strips x 32 lanes x 16B

__device__ float g_G[(size_t)B_ * HW_ * OC];   // [b][hw][o]
__device__ float g_pooled[BN * OC];

__device__ __forceinline__ uint32_t f2tf(float x) {
    uint32_t r; asm("cvt.rna.tf32.f32 %0, %1;" : "=r"(r) : "f"(x)); return r;
}
__device__ __forceinline__ void mma8(float* d, uint4 a, uint32_t b0, uint32_t b1) {
    asm volatile("mma.sync.aligned.m16n8k8.row.col.f32.tf32.tf32.f32 "
        "{%0,%1,%2,%3}, {%4,%5,%6,%7}, {%8,%9}, {%0,%1,%2,%3};"
        : "+f"(d[0]), "+f"(d[1]), "+f"(d[2]), "+f"(d[3])
        : "r"(a.x), "r"(a.y), "r"(a.z), "r"(a.w), "r"(b0), "r"(b1));
}

// ============================================================================
// GEMM: G[b][hw][o] = sum_c Wc[o][c] * F[b][c][hw]   (tf32 mma.sync)
// Persistent 148 CTAs x 256 threads. Warp tile m32 x n32. CTA tile m128 x n64.
// ============================================================================
__global__ __launch_bounds__(256, 1)
void gemm_kernel(const float* __restrict__ features, const float* __restrict__ Wc)
{
    extern __shared__ __align__(16) char dsm[];
    uint32_t* Bs = (uint32_t*)(dsm + AFRAG_BYTES);   // [64 hw][BSTR]

    const int tid = threadIdx.x, wid = tid >> 5, lane = tid & 31;
    const int g = lane >> 2, t4 = lane & 3;

    // ---- one-time: build A fragments (warp w -> m-strip w, o = 16w..16w+15)
    {
        const int o0 = wid * 16;
        for (int k = 0; k < 32; k++) {
            uint4 a;
            a.x = f2tf(__ldg(&Wc[(o0 + g    ) * 256 + k * 8 + t4    ]));
            a.y = f2tf(__ldg(&Wc[(o0 + g + 8) * 256 + k * 8 + t4    ]));
            a.z = f2tf(__ldg(&Wc[(o0 + g    ) * 256 + k * 8 + t4 + 4]));
            a.w = f2tf(__ldg(&Wc[(o0 + g + 8) * 256 + k * 8 + t4 + 4]));
            *(uint4*)(dsm + (((k * 8 + wid) * 32) + lane) * 16) = a;
        }
    }

    const int mg = wid & 3, ng = wid >> 2;     // warp: m-group (o=32mg), n-group (hw=32ng)

    // prefetch first tile: thread = channel, 64 contiguous floats
    float4 f[16];
    int t = blockIdx.x;
    if (t < NTILES) {
        const float4* src = (const float4*)(features
            + ((size_t)((t >> 10) * C_) + tid) * HW_ + (t & 1023) * NT);
        #pragma unroll
        for (int j = 0; j < 16; j++) f[j] = __ldg(&src[j]);
    }

    for (; t < NTILES; t += GRID_GEMM) {
        __syncthreads();                       // prior mma done reading Bs
        // convert + store B tile: Bs[hw][k=tid], conflict-free column writes
        {
            const float* fv = (const float*)f;
            #pragma unroll
            for (int j = 0; j < 64; j++) Bs[j * BSTR + tid] = f2tf(fv[j]);
        }
        __syncthreads();                       // B ready

        // prefetch next tile (hidden under mma phase)
        const int nt = t + GRID_GEMM;
        if (nt < NTILES) {
            const float4* src = (const float4*)(features
                + ((size_t)((nt >> 10) * C_) + tid) * HW_ + (nt & 1023) * NT);
            #pragma unroll
            for (int j = 0; j < 16; j++) f[j] = __ldg(&src[j]);
        }

        // mma phase: m32 x n32 x k256
        float acc[2][4][4];
        #pragma unroll
        for (int mi = 0; mi < 2; mi++)
            #pragma unroll
            for (int ni = 0; ni < 4; ni++)
                #pragma unroll
                for (int q = 0; q < 4; q++) acc[mi][ni][q] = 0.f;

        #pragma unroll 8
        for (int k = 0; k < 32; k++) {
            const uint4 a0 = *(const uint4*)(dsm + ((k * 8 + 2 * mg    ) * 32 + lane) * 16);
            const uint4 a1 = *(const uint4*)(dsm + ((k * 8 + 2 * mg + 1) * 32 + lane) * 16);
            #pragma unroll
            for (int ni = 0; ni < 4; ni++) {
                const uint32_t* bp = Bs + (ng * 32 + ni * 8 + g) * BSTR + k * 8 + t4;
                const uint32_t b0 = bp[0], b1 = bp[4];
                mma8(acc[0][ni], a0, b0, b1);
                mma8(acc[1][ni], a1, b0, b1);
            }
        }

        // epilogue: write D to g_G[b][hw][o]
        {
            const int b = t >> 10, hw0 = (t & 1023) * NT;
            float* gb = g_G + (size_t)b * HW_ * OC;
            #pragma unroll
            for (int mi = 0; mi < 2; mi++)
                #pragma unroll
                for (int ni = 0; ni < 4; ni++) {
                    const int o  = mg * 32 + mi * 16 + g;
                    const int hw = hw0 + ng * 32 + ni * 8 + 2 * t4;
                    float* p = gb + (size_t)hw * OC + o;
                    p[0]      = acc[mi][ni][0];
                    p[OC]     = acc[mi][ni][1];
                    p[8]      = acc[mi][ni][2];
                    p[OC + 8] = acc[mi][ni][3];
                }
        }
    }
}

// ============================================================================
// Gather: bilinear on G + bias + relu + 7x7 mean. Block = vertex, thread = o.
// ============================================================================
__global__ __launch_bounds__(128)
void gather_pool_kernel(const float* __restrict__ vertices, const float* __restrict__ bc)
{
    const int bid = blockIdx.x, o = threadIdx.x, b = bid >> 10;
    const float fx = vertices[bid * 2] - 3.5f, fy = vertices[bid * 2 + 1] - 3.5f;
    int ix = (int)floorf(fx), iy = (int)floorf(fy);
    const float lx = fx - ix, ly = fy - iy;
    ix = max(0, min(ix, W_ - 8)); iy = max(0, min(iy, H_ - 8));
    const float hx = 1.f - lx, hy = 1.f - ly;
    const float w00 = hy * hx, w01 = hy * lx, w10 = ly * hx, w11 = ly * lx;
    const float bias = __ldg(&bc[o]);

    const float* base = g_G + ((size_t)b * HW_ + (size_t)iy * W_ + ix) * OC + o;
    float prev[8], cur[8], acc = 0.f;
    #pragma unroll
    for (int r = 0; r < 8; r++) {
        #pragma unroll
        for (int c = 0; c < 8; c++) cur[c] = __ldg(base + ((size_t)r * W_ + c) * OC);
        if (r > 0) {
            #pragma unroll
            for (int px = 0; px < 7; px++) {
                const float v = w00 * prev[px] + w01 * prev[px + 1]
                              + w10 * cur[px]  + w11 * cur[px + 1] + bias;
                acc += fmaxf(v, 0.f);
            }
        }
        #pragma unroll
        for (int c = 0; c < 8; c++) prev[c] = cur[c];
    }
    g_pooled[bid * OC + o] = acc * (1.0f / 49.0f);
}

// ============================================================================
// MLP + heads. 16 vertices/block, 256 threads. smem 30.7 KB (h2T aliases pT).
// ============================================================================
__global__ __launch_bounds__(256)
void mlp_kernel(const float* __restrict__ W1, const float* __restrict__ b1,
                const float* __restrict__ W2, const float* __restrict__ b2,
                const float* __restrict__ Wa, const float* __restrict__ ba,
                const float* __restrict__ Wr, const float* __restrict__ br,
                const float* __restrict__ Ww, const float* __restrict__ bw,
                float* __restrict__ out)
{
    __shared__ __align__(16) float sA[128 * 20];   // pT, later h2T
    __shared__ __align__(16) float sH[256 * 20];   // h1T

    const int tid = threadIdx.x, base = blockIdx.x * 16;

    for (int e = tid; e < 16 * 128; e += 256) {
        const int v = e >> 7, k = e & 127;
        sA[k * 20 + v] = g_pooled[(base + v) * 128 + k];
    }
    __syncthreads();

    float acc[16];
    #pragma unroll
    for (int v = 0; v < 16; v++) acc[v] = 0.f;
    {
        const float4* w1r = (const float4*)(W1 + tid * 128);
        #pragma unroll 4
        for (int k4 = 0; k4 < 32; ++k4) {
            const float4 w4 = __ldg(&w1r[k4]);
            const float wk[4] = {w4.x, w4.y, w4.z, w4.w};
            #pragma unroll
            for (int u = 0; u < 4; ++u) {
                const float w = wk[u];
                const float4* pr = (const float4*)&sA[(k4 * 4 + u) * 20];
                const float4 a0 = pr[0], a1 = pr[1], a2 = pr[2], a3 = pr[3];
                acc[0] += w*a0.x;  acc[1] += w*a0.y;  acc[2] += w*a0.z;  acc[3] += w*a0.w;
                acc[4] += w*a1.x;  acc[5] += w*a1.y;  acc[6] += w*a1.z;  acc[7] += w*a1.w;
                acc[8] += w*a2.x;  acc[9] += w*a2.y;  acc[10] += w*a2.z; acc[11] += w*a2.w;
                acc[12] += w*a3.x; acc[13] += w*a3.y; acc[14] += w*a3.z; acc[15] += w*a3.w;
            }
        }
    }
    {
        const float bb = __ldg(&b1[tid]);
        #pragma unroll
        for (int v = 0; v < 16; v++) sH[tid * 20 + v] = fmaxf(acc[v] + bb, 0.f);
    }
    __syncthreads();

    const int c2 = tid & 127, vh = tid >> 7;
    float acc2[8];
    #pragma unroll
    for (int i = 0; i < 8; i++) acc2[i] = 0.f;
    {
        const float4* w2r = (const float4*)(W2 + c2 * 256);
        #pragma unroll 4
        for (int k4 = 0; k4 < 64; ++k4) {
            const float4 w4 = __ldg(&w2r[k4]);
            const float wk[4] = {w4.x, w4.y, w4.z, w4.w};
            #pragma unroll
            for (int u = 0; u < 4; ++u) {
                const float w = wk[u];
                const float4* hr = (const float4*)&sH[(k4 * 4 + u) * 20];
                const float4 x0 = hr[vh * 2], x1 = hr[vh * 2 + 1];
                acc2[0] += w*x0.x; acc2[1] += w*x0.y; acc2[2] += w*x0.z; acc2[3] += w*x0.w;
                acc2[4] += w*x1.x; acc2[5] += w*x1.y; acc2[6] += w*x1.z; acc2[7] += w*x1.w;
            }
        }
    }
    __syncthreads();   // pT dead; reuse sA as h2T
    {
        const float b2v = __ldg(&b2[c2]);
        #pragma unroll
        for (int i = 0; i < 8; i++) sA[c2 * 20 + vh * 8 + i] = fmaxf(acc2[i] + b2v, 0.f);
    }
    __syncthreads();

    if (tid < 64) {
        const int v = tid >> 2, hd = tid & 3;
        const float* wr; float bias;
        if      (hd == 0) { wr = Wa;       bias = __ldg(&ba[0]); }
        else if (hd == 1) { wr = Wa + 128; bias = __ldg(&ba[1]); }
        else if (hd == 2) { wr = Wr;       bias = __ldg(&br[0]); }
        else              { wr = Ww;       bias = __ldg(&bw[0]); }
        float s = bias;
        #pragma unroll 4
        for (int k = 0; k < 128; k++) s = fmaf(__ldg(&wr[k]), sA[k * 20 + v], s);
        const int gidx = base + v;
        if      (hd <  2) out[gidx * 2 + hd] = s;
        else if (hd == 2) out[2 * BN + gidx] = s;
        else              out[3 * BN + gidx] = s;
    }
}

// ============================================================================
extern "C" void kernel_launch(void* const* d_in, const int* in_sizes, int n_in,
                              void* d_out, int out_size)
{
    const float* features = (const float*)d_in[0];
    const float* vertices = (const float*)d_in[1];
    const float* Wc = (const float*)d_in[2];
    const float* bc = (const float*)d_in[3];
    const float* W1 = (const float*)d_in[4];
    const float* b1 = (const float*)d_in[5];
    const float* W2 = (const float*)d_in[6];
    const float* b2 = (const float*)d_in[7];
    const float* Wa = (const float*)d_in[8];
    const float* ba = (const float*)d_in[9];
    const float* Wr = (const float*)d_in[10];
    const float* br = (const float*)d_in[11];
    const float* Ww = (const float*)d_in[12];
    const float* bw = (const float*)d_in[13];
    float* out = (float*)d_out;

    const int smem_dyn = AFRAG_BYTES + 64 * BSTR * 4;   // 131072 + 66560 = 197632
    cudaFuncSetAttribute(gemm_kernel, cudaFuncAttributeMaxDynamicSharedMemorySize, smem_dyn);

    gemm_kernel<<<GRID_GEMM, 256, smem_dyn>>>(features, Wc);
    gather_pool_kernel<<<BN, 128>>>(vertices, bc);
    mlp_kernel<<<BN / 16, 256>>>(W1, b1, W2, b2, Wa, ba, Wr, br, Ww, bw, out);
}

// round 6
// speedup vs baseline: 2.6206x; 1.0599x over previous
#include <cuda_runtime.h>
#include <cstdint>

#define W_  256
#define H_  256
#define C_  256
#define HW_ 65536
#define B_  4
#define BN  4096
#define OC  128
#define NT  128
#define NTILES 2048        // B_*HW_/NT
#define GRID_GEMM 148
#define BSTR 136           // B smem row stride (floats), k-major
#define AFRAG_BYTES 131072
#define BS_BYTES (128*BSTR*4)

__device__ float g_G[(size_t)B_ * HW_ * OC];   // [b][hw][o]
__device__ float g_pooled[BN * OC];

__device__ __forceinline__ uint32_t f2tf(float x) {
    uint32_t r; asm("cvt.rna.tf32.f32 %0, %1;" : "=r"(r) : "f"(x)); return r;
}
__device__ __forceinline__ void mma8(float* d, uint4 a, uint32_t b0, uint32_t b1) {
    asm volatile("mma.sync.aligned.m16n8k8.row.col.f32.tf32.tf32.f32 "
        "{%0,%1,%2,%3}, {%4,%5,%6,%7}, {%8,%9}, {%0,%1,%2,%3};"
        : "+f"(d[0]), "+f"(d[1]), "+f"(d[2]), "+f"(d[3])
        : "r"(a.x), "r"(a.y), "r"(a.z), "r"(a.w), "r"(b0), "r"(b1));
}

// ============================================================================
// GEMM: G[b][hw][o] = sum_c Wc[o][c]*F[b][c][hw].  tf32 mma.sync.
// 512 threads (16 warps), persistent. CTA tile m128 x n128, warp m32 x n32.
// K processed in two 128-chunks; B smem k-major [128k][BSTR], conflict-free.
// ============================================================================
__global__ __launch_bounds__(512, 1)
void gemm_kernel(const float* __restrict__ features, const float* __restrict__ Wc)
{
    extern __shared__ __align__(16) char dsm[];
    uint32_t* Bs = (uint32_t*)(dsm + AFRAG_BYTES);

    const int tid = threadIdx.x, wid = tid >> 5, lane = tid & 31;
    const int g = lane >> 2, t4 = lane & 3;
    const int mg = wid & 3, ng = wid >> 2;       // m-group (o), n-group (hw)

    // ---- one-time: A fragments (warps 0..7; warp w -> m16 strip w) ----
    if (wid < 8) {
        const int o0 = wid * 16;
        for (int k = 0; k < 32; k++) {
            uint4 a;
            a.x = f2tf(__ldg(&Wc[(o0 + g    ) * 256 + k * 8 + t4    ]));
            a.y = f2tf(__ldg(&Wc[(o0 + g + 8) * 256 + k * 8 + t4    ]));
            a.z = f2tf(__ldg(&Wc[(o0 + g    ) * 256 + k * 8 + t4 + 4]));
            a.w = f2tf(__ldg(&Wc[(o0 + g + 8) * 256 + k * 8 + t4 + 4]));
            *(uint4*)(dsm + (((k * 8 + wid) * 32) + lane) * 16) = a;
        }
    }

    // chunk LDG: warp w covers channels kc*128 + w*8 .. +7, lane -> 4 hw
    float4 rf[8];
    int t = blockIdx.x;
    if (t < NTILES) {
        const float* s = features + ((size_t)((t >> 9) * C_ + wid * 8)) * HW_
                       + (t & 511) * NT + 4 * lane;
        #pragma unroll
        for (int j = 0; j < 8; j++) rf[j] = __ldg((const float4*)(s + (size_t)j * HW_));
    }

    for (; t < NTILES; t += GRID_GEMM) {
        const int b = t >> 9, hw0 = (t & 511) * NT;
        float acc[2][4][4];
        #pragma unroll
        for (int mi = 0; mi < 2; mi++)
            #pragma unroll
            for (int ni = 0; ni < 4; ni++)
                #pragma unroll
                for (int q = 0; q < 4; q++) acc[mi][ni][q] = 0.f;

        #pragma unroll
        for (int kc = 0; kc < 2; kc++) {
            __syncthreads();                    // Bs free
            // STS chunk (cvt + STS.128, conflict-free)
            #pragma unroll
            for (int j = 0; j < 8; j++) {
                uint4 v;
                v.x = f2tf(rf[j].x); v.y = f2tf(rf[j].y);
                v.z = f2tf(rf[j].z); v.w = f2tf(rf[j].w);
                *(uint4*)&Bs[(wid * 8 + j) * BSTR + 4 * lane] = v;
            }
            __syncthreads();                    // B ready
            // prefetch: kc==0 -> chunk1 of this tile; kc==1 -> chunk0 of next
            {
                const int nt = (kc == 0) ? t : t + GRID_GEMM;
                if (nt < NTILES) {
                    const int kcn = kc ^ 1;
                    const float* s = features
                        + ((size_t)((nt >> 9) * C_ + kcn * 128 + wid * 8)) * HW_
                        + (nt & 511) * NT + 4 * lane;
                    #pragma unroll
                    for (int j = 0; j < 8; j++)
                        rf[j] = __ldg((const float4*)(s + (size_t)j * HW_));
                }
            }
            // mma: 16 ksteps of this chunk
            #pragma unroll 8
            for (int kk = 0; kk < 16; kk++) {
                const int ka = kc * 16 + kk;
                const uint4 a0 = *(const uint4*)(dsm + ((ka * 8 + 2 * mg    ) * 32 + lane) * 16);
                const uint4 a1 = *(const uint4*)(dsm + ((ka * 8 + 2 * mg + 1) * 32 + lane) * 16);
                #pragma unroll
                for (int ni = 0; ni < 4; ni++) {
                    const uint32_t* bp = Bs + (kk * 8 + t4) * BSTR + ng * 32 + ni * 8 + g;
                    const uint32_t b0 = bp[0], b1 = bp[4 * BSTR];
                    mma8(acc[0][ni], a0, b0, b1);
                    mma8(acc[1][ni], a1, b0, b1);
                }
            }
        }
        // epilogue: D -> g_G[b][hw][o]
        {
            float* gb = g_G + (size_t)b * HW_ * OC;
            #pragma unroll
            for (int mi = 0; mi < 2; mi++)
                #pragma unroll
                for (int ni = 0; ni < 4; ni++) {
                    const int o  = mg * 32 + mi * 16 + g;
                    const int hw = hw0 + ng * 32 + ni * 8 + 2 * t4;
                    float* p = gb + (size_t)hw * OC + o;
                    p[0]      = acc[mi][ni][0];
                    p[OC]     = acc[mi][ni][1];
                    p[8]      = acc[mi][ni][2];
                    p[OC + 8] = acc[mi][ni][3];
                }
        }
    }
}

// ============================================================================
// Gather: bilinear on G + bias + relu + 7x7 mean. Block = vertex, thread = o.
// ============================================================================
__global__ __launch_bounds__(128)
void gather_pool_kernel(const float* __restrict__ vertices, const float* __restrict__ bc)
{
    const int bid = blockIdx.x, o = threadIdx.x, b = bid >> 10;
    const float fx = vertices[bid * 2] - 3.5f, fy = vertices[bid * 2 + 1] - 3.5f;
    int ix = (int)floorf(fx), iy = (int)floorf(fy);
    const float lx = fx - ix, ly = fy - iy;
    ix = max(0, min(ix, W_ - 8)); iy = max(0, min(iy, H_ - 8));
    const float hx = 1.f - lx, hy = 1.f - ly;
    const float w00 = hy * hx, w01 = hy * lx, w10 = ly * hx, w11 = ly * lx;
    const float bias = __ldg(&bc[o]);

    const float* base = g_G + ((size_t)b * HW_ + (size_t)iy * W_ + ix) * OC + o;
    float prev[8], cur[8], acc = 0.f;
    #pragma unroll
    for (int r = 0; r < 8; r++) {
        #pragma unroll
        for (int c = 0; c < 8; c++) cur[c] = __ldg(base + ((size_t)r * W_ + c) * OC);
        if (r > 0) {
            #pragma unroll
            for (int px = 0; px < 7; px++) {
                const float v = w00 * prev[px] + w01 * prev[px + 1]
                              + w10 * cur[px]  + w11 * cur[px + 1] + bias;
                acc += fmaxf(v, 0.f);
            }
        }
        #pragma unroll
        for (int c = 0; c < 8; c++) prev[c] = cur[c];
    }
    g_pooled[bid * OC + o] = acc * (1.0f / 49.0f);
}

// ============================================================================
// MLP + heads. 8 vertices/block (512 blocks), 256 threads, stride-12 smem.
// ============================================================================
#define BV 8
__global__ __launch_bounds__(256)
void mlp_kernel(const float* __restrict__ W1, const float* __restrict__ b1,
                const float* __restrict__ W2, const float* __restrict__ b2,
                const float* __restrict__ Wa, const float* __restrict__ ba,
                const float* __restrict__ Wr, const float* __restrict__ br,
                const float* __restrict__ Ww, const float* __restrict__ bw,
                float* __restrict__ out)
{
    __shared__ __align__(16) float sA[128 * 12];   // pooled / later h2T
    __shared__ __align__(16) float sH[256 * 12];   // h1T

    const int tid = threadIdx.x, base = blockIdx.x * BV;

    for (int e = tid; e < BV * 128; e += 256) {
        const int v = e & 7, k = e >> 3;
        sA[k * 12 + v] = g_pooled[(base + v) * 128 + k];
    }
    __syncthreads();

    // ---- h1: thread = output channel o (256), 8 vertices ----
    float acc[8];
    #pragma unroll
    for (int v = 0; v < 8; v++) acc[v] = 0.f;
    {
        const float4* w1r = (const float4*)(W1 + tid * 128);
        #pragma unroll 4
        for (int k8 = 0; k8 < 16; ++k8) {
            const float4 wa = __ldg(&w1r[2 * k8]), wb = __ldg(&w1r[2 * k8 + 1]);
            const float wk[8] = {wa.x, wa.y, wa.z, wa.w, wb.x, wb.y, wb.z, wb.w};
            #pragma unroll
            for (int u = 0; u < 8; ++u) {
                const float w = wk[u];
                const float4* pr = (const float4*)&sA[(k8 * 8 + u) * 12];
                const float4 a0 = pr[0], a1 = pr[1];
                acc[0] += w * a0.x; acc[1] += w * a0.y; acc[2] += w * a0.z; acc[3] += w * a0.w;
                acc[4] += w * a1.x; acc[5] += w * a1.y; acc[6] += w * a1.z; acc[7] += w * a1.w;
            }
        }
    }
    {
        const float bb = __ldg(&b1[tid]);
        float4 r0, r1;
        r0.x = fmaxf(acc[0] + bb, 0.f); r0.y = fmaxf(acc[1] + bb, 0.f);
        r0.z = fmaxf(acc[2] + bb, 0.f); r0.w = fmaxf(acc[3] + bb, 0.f);
        r1.x = fmaxf(acc[4] + bb, 0.f); r1.y = fmaxf(acc[5] + bb, 0.f);
        r1.z = fmaxf(acc[6] + bb, 0.f); r1.w = fmaxf(acc[7] + bb, 0.f);
        ((float4*)&sH[tid * 12])[0] = r0;
        ((float4*)&sH[tid * 12])[1] = r1;
    }
    __syncthreads();

    // ---- h2: thread = (channel c2, vertex-half vh of 4) ----
    const int c2 = tid & 127, vh = tid >> 7;
    float acc2[4];
    #pragma unroll
    for (int i = 0; i < 4; i++) acc2[i] = 0.f;
    {
        const float4* w2r = (const float4*)(W2 + c2 * 256);
        #pragma unroll 4
        for (int k8 = 0; k8 < 32; ++k8) {
            const float4 wa = __ldg(&w2r[2 * k8]), wb = __ldg(&w2r[2 * k8 + 1]);
            const float wk[8] = {wa.x, wa.y, wa.z, wa.w, wb.x, wb.y, wb.z, wb.w};
            #pragma unroll
            for (int u = 0; u < 8; ++u) {
                const float w = wk[u];
                const float4 x = ((const float4*)&sH[(k8 * 8 + u) * 12])[vh];
                acc2[0] += w * x.x; acc2[1] += w * x.y;
                acc2[2] += w * x.z; acc2[3] += w * x.w;
            }
        }
    }
    {
        const float b2v = __ldg(&b2[c2]);
        float4 r;
        r.x = fmaxf(acc2[0] + b2v, 0.f); r.y = fmaxf(acc2[1] + b2v, 0.f);
        r.z = fmaxf(acc2[2] + b2v, 0.f); r.w = fmaxf(acc2[3] + b2v, 0.f);
        *(float4*)&sA[c2 * 12 + vh * 4] = r;
    }
    __syncthreads();

    // ---- heads ----
    if (tid < BV * 4) {
        const int v = tid >> 2, hd = tid & 3;
        const float* wr; float bias;
        if      (hd == 0) { wr = Wa;       bias = __ldg(&ba[0]); }
        else if (hd == 1) { wr = Wa + 128; bias = __ldg(&ba[1]); }
        else if (hd == 2) { wr = Wr;       bias = __ldg(&br[0]); }
        else              { wr = Ww;       bias = __ldg(&bw[0]); }
        float s = bias;
        #pragma unroll 4
        for (int k = 0; k < 128; k++) s = fmaf(__ldg(&wr[k]), sA[k * 12 + v], s);
        const int gidx = base + v;
        if      (hd <  2) out[gidx * 2 + hd] = s;
        else if (hd == 2) out[2 * BN + gidx] = s;
        else              out[3 * BN + gidx] = s;
    }
}

// ============================================================================
extern "C" void kernel_launch(void* const* d_in, const int* in_sizes, int n_in,
                              void* d_out, int out_size)
{
    const float* features = (const float*)d_in[0];
    const float* vertices = (const float*)d_in[1];
    const float* Wc = (const float*)d_in[2];
    const float* bc = (const float*)d_in[3];
    const float* W1 = (const float*)d_in[4];
    const float* b1 = (const float*)d_in[5];
    const float* W2 = (const float*)d_in[6];
    const float* b2 = (const float*)d_in[7];
    const float* Wa = (const float*)d_in[8];
    const float* ba = (const float*)d_in[9];
    const float* Wr = (const float*)d_in[10];
    const float* br = (const float*)d_in[11];
    const float* Ww = (const float*)d_in[12];
    const float* bw = (const float*)d_in[13];
    float* out = (float*)d_out;

    const int smem_dyn = AFRAG_BYTES + BS_BYTES;   // 131072 + 69632 = 200704
    cudaFuncSetAttribute(gemm_kernel, cudaFuncAttributeMaxDynamicSharedMemorySize, smem_dyn);

    gemm_kernel<<<GRID_GEMM, 512, smem_dyn>>>(features, Wc);
    gather_pool_kernel<<<BN, 128>>>(vertices, bc);
    mlp_kernel<<<BN / BV, 256>>>(W1, b1, W2, b2, Wa, ba, Wr, br, Ww, bw, out);
}

// round 9
// speedup vs baseline: 2.9527x; 1.1267x over previous
#include <cuda_runtime.h>
#include <cstdint>

#define W_  256
#define H_  256
#define C_  256
#define HW_ 65536
#define B_  4
#define BN  4096
#define OC  128
#define NT  256
#define NTILES 1024            // B_*HW_/NT
#define GRID_GEMM 148
#define AFRAG_BYTES 131072
#define CHUNK_BYTES 32768      // 32k x 256hw x 4B
#define GEMM_SMEM (AFRAG_BYTES + 3*CHUNK_BYTES)   // 229376

__device__ float g_G[(size_t)B_ * HW_ * OC];   // [b][hw][o]
__device__ float g_pooled[BN * OC];

__device__ __forceinline__ uint32_t f2tf(float x) {
    uint32_t r; asm("cvt.rna.tf32.f32 %0, %1;" : "=r"(r) : "f"(x)); return r;
}
__device__ __forceinline__ uint32_t s2u(const void* p) {
    uint32_t a;
    asm("{ .reg .u64 t; cvta.to.shared.u64 t, %1; cvt.u32.u64 %0, t; }" : "=r"(a) : "l"(p));
    return a;
}
__device__ __forceinline__ void mma8(float* d, uint4 a, uint32_t b0, uint32_t b1) {
    asm volatile("mma.sync.aligned.m16n8k8.row.col.f32.tf32.tf32.f32 "
        "{%0,%1,%2,%3}, {%4,%5,%6,%7}, {%8,%9}, {%0,%1,%2,%3};"
        : "+f"(d[0]), "+f"(d[1]), "+f"(d[2]), "+f"(d[3])
        : "r"(a.x), "r"(a.y), "r"(a.z), "r"(a.w), "r"(b0), "r"(b1));
}

// issue one k32 x hw256 feature chunk via cp.async (XOR-swizzled), commit group.
__device__ __forceinline__ void issue_chunk(const float* __restrict__ f,
                                            int t, int c, uint32_t dst_base, int tid)
{
    if (t < NTILES) {
        const int b = t >> 8, hw0 = (t & 255) * NT;
        const int row = tid >> 3;
        const int col0 = (tid & 7) * 32;
        const float* src = f + ((size_t)(b * C_ + c * 32 + row)) * HW_ + hw0 + col0;
        #pragma unroll
        for (int j = 0; j < 8; j++) {
            const int col  = col0 + j * 4;
            const int colp = col ^ ((row & 3) << 3);
            const uint32_t dst = dst_base + ((uint32_t)(row * 256 + colp)) * 4u;
            asm volatile("cp.async.cg.shared.global [%0], [%1], 16;"
                         :: "r"(dst), "l"(src + j * 4) : "memory");
        }
    }
    asm volatile("cp.async.commit_group;" ::: "memory");
}

// ============================================================================
// GEMM: G[b][hw][o] = sum_c Wc[o][c]*F[b][c][hw].  tf32 mma.sync.
// 256 threads (8 warps). CTA tile m128 x n256, warp tile m64 x n64.
// B streamed raw via cp.async; rounded rna->tf32 at the LDS->mma boundary.
// ============================================================================
__global__ __launch_bounds__(256, 1)
void gemm_kernel(const float* __restrict__ features, const float* __restrict__ Wc)
{
    extern __shared__ __align__(16) char dsm[];
    const uint32_t bs_u = s2u(dsm) + AFRAG_BYTES;

    const int tid = threadIdx.x, wid = tid >> 5, lane = tid & 31;
    const int g = lane >> 2, t4 = lane & 3;
    const int mg = wid & 1, ng = wid >> 1;        // m-group (o 64), n-group (hw 64)

    // start streaming chunks 0..2 immediately (hide DRAM under A build)
    int tn = blockIdx.x, cn = 0;
    #pragma unroll
    for (int i = 0; i < 3; i++) {
        issue_chunk(features, tn, cn, bs_u + i * CHUNK_BYTES, tid);
        if (++cn == 8) { cn = 0; tn += GRID_GEMM; }
    }

    // A fragments: warp w builds m16 strip w (o = 16w..16w+15), rna tf32
    {
        const int o0 = wid * 16;
        for (int k = 0; k < 32; k++) {
            uint4 a;
            a.x = f2tf(__ldg(&Wc[(o0 + g    ) * 256 + k * 8 + t4    ]));
            a.y = f2tf(__ldg(&Wc[(o0 + g + 8) * 256 + k * 8 + t4    ]));
            a.z = f2tf(__ldg(&Wc[(o0 + g    ) * 256 + k * 8 + t4 + 4]));
            a.w = f2tf(__ldg(&Wc[(o0 + g + 8) * 256 + k * 8 + t4 + 4]));
            *(uint4*)(dsm + (((k * 8 + wid) * 32) + lane) * 16) = a;
        }
    }

    int bufi = 0;
    for (int t = blockIdx.x; t < NTILES; t += GRID_GEMM) {
        float acc[4][8][4];
        #pragma unroll
        for (int mi = 0; mi < 4; mi++)
            #pragma unroll
            for (int ni = 0; ni < 8; ni++)
                #pragma unroll
                for (int q = 0; q < 4; q++) acc[mi][ni][q] = 0.f;

        #pragma unroll
        for (int c = 0; c < 8; c++) {
            asm volatile("cp.async.wait_group 2;" ::: "memory");
            __syncthreads();                       // chunk ready (and A frags on c==0)
            const float* bb = (const float*)(dsm + AFRAG_BYTES + bufi * CHUNK_BYTES);
            #pragma unroll
            for (int kkl = 0; kkl < 4; kkl++) {
                const int ka = c * 4 + kkl;
                uint4 a[4];
                #pragma unroll
                for (int mi = 0; mi < 4; mi++)
                    a[mi] = *(const uint4*)(dsm + ((ka * 8 + mg * 4 + mi) * 32 + lane) * 16);
                #pragma unroll
                for (int ni = 0; ni < 8; ni++) {
                    const int colp = (ng * 64 + ni * 8 + g) ^ (t4 << 3);
                    // round-to-nearest tf32 (raw bits would truncate -> biased)
                    const uint32_t b0 = f2tf(bb[(kkl * 8 + t4    ) * 256 + colp]);
                    const uint32_t b1 = f2tf(bb[(kkl * 8 + t4 + 4) * 256 + colp]);
                    #pragma unroll
                    for (int mi = 0; mi < 4; mi++) mma8(acc[mi][ni], a[mi], b0, b1);
                }
            }
            __syncthreads();                       // done reading this buffer
            issue_chunk(features, tn, cn, bs_u + bufi * CHUNK_BYTES, tid);
            if (++cn == 8) { cn = 0; tn += GRID_GEMM; }
            bufi = (bufi == 2) ? 0 : bufi + 1;
        }
        // epilogue: D -> g_G[b][hw][o]
        {
            const int b = t >> 8, hw0 = (t & 255) * NT;
            float* gb = g_G + (size_t)b * HW_ * OC;
            #pragma unroll
            for (int mi = 0; mi < 4; mi++)
                #pragma unroll
                for (int ni = 0; ni < 8; ni++) {
                    const int o  = mg * 64 + mi * 16 + g;
                    const int hw = hw0 + ng * 64 + ni * 8 + 2 * t4;
                    float* p = gb + (size_t)hw * OC + o;
                    p[0]      = acc[mi][ni][0];
                    p[OC]     = acc[mi][ni][1];
                    p[8]      = acc[mi][ni][2];
                    p[OC + 8] = acc[mi][ni][3];
                }
        }
    }
}

// ============================================================================
// Gather: bilinear on G + bias + relu + 7x7 mean. Block = vertex, thread = o.
// ============================================================================
__global__ __launch_bounds__(128)
void gather_pool_kernel(const float* __restrict__ vertices, const float* __restrict__ bc)
{
    const int bid = blockIdx.x, o = threadIdx.x, b = bid >> 10;
    const float fx = vertices[bid * 2] - 3.5f, fy = vertices[bid * 2 + 1] - 3.5f;
    int ix = (int)floorf(fx), iy = (int)floorf(fy);
    const float lx = fx - ix, ly = fy - iy;
    ix = max(0, min(ix, W_ - 8)); iy = max(0, min(iy, H_ - 8));
    const float hx = 1.f - lx, hy = 1.f - ly;
    const float w00 = hy * hx, w01 = hy * lx, w10 = ly * hx, w11 = ly * lx;
    const float bias = __ldg(&bc[o]);

    const float* base = g_G + ((size_t)b * HW_ + (size_t)iy * W_ + ix) * OC + o;
    float prev[8], cur[8], acc = 0.f;
    #pragma unroll
    for (int r = 0; r < 8; r++) {
        #pragma unroll
        for (int c = 0; c < 8; c++) cur[c] = __ldg(base + ((size_t)r * W_ + c) * OC);
        if (r > 0) {
            #pragma unroll
            for (int px = 0; px < 7; px++) {
                const float v = w00 * prev[px] + w01 * prev[px + 1]
                              + w10 * cur[px]  + w11 * cur[px + 1] + bias;
                acc += fmaxf(v, 0.f);
            }
        }
        #pragma unroll
        for (int c = 0; c < 8; c++) prev[c] = cur[c];
    }
    g_pooled[bid * OC + o] = acc * (1.0f / 49.0f);
}

// ============================================================================
// MLP + heads. 32 vertices/block (128 blocks), 256 threads.
// Register blocking: h1 = 4 outputs x 8 vertices, h2 = 4 x 4.
// Dynamic smem: sP[128][36] + sH[256][36] = 55,296 B.
// ============================================================================
#define MBV 32
#define SPAD 36
__global__ __launch_bounds__(256)
void mlp_kernel(const float* __restrict__ W1, const float* __restrict__ b1,
                const float* __restrict__ W2, const float* __restrict__ b2,
                const float* __restrict__ Wa, const float* __restrict__ ba,
                const float* __restrict__ Wr, const float* __restrict__ br,
                const float* __restrict__ Ww, const float* __restrict__ bw,
                float* __restrict__ out)
{
    extern __shared__ __align__(16) float ms[];
    float* sP = ms;                 // [128][SPAD] pooled (k-major), later h2T
    float* sH = ms + 128 * SPAD;    // [256][SPAD] h1T

    const int tid = threadIdx.x, base = blockIdx.x * MBV;

    for (int e = tid; e < MBV * 128; e += 256) {
        const int v = e >> 7, k = e & 127;
        sP[k * SPAD + v] = g_pooled[(base + v) * 128 + k];
    }
    __syncthreads();

    // ---- h1: thread = (oq 64, vq 4): outputs oq*4..+3, vertices vq*8..+7 ----
    {
        const int oq = tid >> 2, vq = tid & 3;
        float acc[4][8];
        #pragma unroll
        for (int r = 0; r < 4; r++)
            #pragma unroll
            for (int j = 0; j < 8; j++) acc[r][j] = 0.f;
        #pragma unroll 2
        for (int k4 = 0; k4 < 32; ++k4) {
            float4 wv[4];
            #pragma unroll
            for (int r = 0; r < 4; r++)
                wv[r] = __ldg((const float4*)(W1 + (oq * 4 + r) * 128 + k4 * 4));
            #pragma unroll
            for (int u = 0; u < 4; ++u) {
                const int k = k4 * 4 + u;
                const float4 va = *(const float4*)&sP[k * SPAD + vq * 8];
                const float4 vb = *(const float4*)&sP[k * SPAD + vq * 8 + 4];
                #pragma unroll
                for (int r = 0; r < 4; r++) {
                    const float w = (u == 0) ? wv[r].x : (u == 1) ? wv[r].y
                                  : (u == 2) ? wv[r].z : wv[r].w;
                    acc[r][0] += w * va.x; acc[r][1] += w * va.y;
                    acc[r][2] += w * va.z; acc[r][3] += w * va.w;
                    acc[r][4] += w * vb.x; acc[r][5] += w * vb.y;
                    acc[r][6] += w * vb.z; acc[r][7] += w * vb.w;
                }
            }
        }
        #pragma unroll
        for (int r = 0; r < 4; r++) {
            const int o = oq * 4 + r;
            const float bb = __ldg(&b1[o]);
            float4 r0, r1;
            r0.x = fmaxf(acc[r][0] + bb, 0.f); r0.y = fmaxf(acc[r][1] + bb, 0.f);
            r0.z = fmaxf(acc[r][2] + bb, 0.f); r0.w = fmaxf(acc[r][3] + bb, 0.f);
            r1.x = fmaxf(acc[r][4] + bb, 0.f); r1.y = fmaxf(acc[r][5] + bb, 0.f);
            r1.z = fmaxf(acc[r][6] + bb, 0.f); r1.w = fmaxf(acc[r][7] + bb, 0.f);
            *(float4*)&sH[o * SPAD + vq * 8]     = r0;
            *(float4*)&sH[o * SPAD + vq * 8 + 4] = r1;
        }
    }
    __syncthreads();

    // ---- h2: thread = (oq2 32, vq2 8): outputs oq2*4..+3, vertices vq2*4..+3 ----
    {
        const int oq2 = tid >> 3, vq2 = tid & 7;
        float acc2[4][4];
        #pragma unroll
        for (int r = 0; r < 4; r++)
            #pragma unroll
            for (int j = 0; j < 4; j++) acc2[r][j] = 0.f;
        #pragma unroll 2
        for (int k4 = 0; k4 < 64; ++k4) {
            float4 wv[4];
            #pragma unroll
            for (int r = 0; r < 4; r++)
                wv[r] = __ldg((const float4*)(W2 + (oq2 * 4 + r) * 256 + k4 * 4));
            #pragma unroll
            for (int u = 0; u < 4; ++u) {
                const int k = k4 * 4 + u;
                const float4 va = *(const float4*)&sH[k * SPAD + vq2 * 4];
                #pragma unroll
                for (int r = 0; r < 4; r++) {
                    const float w = (u == 0) ? wv[r].x : (u == 1) ? wv[r].y
                                  : (u == 2) ? wv[r].z : wv[r].w;
                    acc2[r][0] += w * va.x; acc2[r][1] += w * va.y;
                    acc2[r][2] += w * va.z; acc2[r][3] += w * va.w;
                }
            }
        }
        __syncthreads();   // all h1 reads of sP done; reuse sP as h2T
        #pragma unroll
        for (int r = 0; r < 4; r++) {
            const int o = oq2 * 4 + r;
            const float bb = __ldg(&b2[o]);
            float4 rr;
            rr.x = fmaxf(acc2[r][0] + bb, 0.f); rr.y = fmaxf(acc2[r][1] + bb, 0.f);
            rr.z = fmaxf(acc2[r][2] + bb, 0.f); rr.w = fmaxf(acc2[r][3] + bb, 0.f);
            *(float4*)&sP[o * SPAD + vq2 * 4] = rr;
        }
    }
    __syncthreads();

    // ---- heads ----
    if (tid < MBV * 4) {
        const int v = tid >> 2, hd = tid & 3;
        const float* wr; float bias;
        if      (hd == 0) { wr = Wa;       bias = __ldg(&ba[0]); }
        else if (hd == 1) { wr = Wa + 128; bias = __ldg(&ba[1]); }
        else if (hd == 2) { wr = Wr;       bias = __ldg(&br[0]); }
        else              { wr = Ww;       bias = __ldg(&bw[0]); }
        float s = bias;
        #pragma unroll 4
        for (int k = 0; k < 128; k++) s = fmaf(__ldg(&wr[k]), sP[k * SPAD + v], s);
        const int gidx = base + v;
        if      (hd <  2) out[gidx * 2 + hd] = s;
        else if (hd == 2) out[2 * BN + gidx] = s;
        else              out[3 * BN + gidx] = s;
    }
}

// ============================================================================
extern "C" void kernel_launch(void* const* d_in, const int* in_sizes, int n_in,
                              void* d_out, int out_size)
{
    const float* features = (const float*)d_in[0];
    const float* vertices = (const float*)d_in[1];
    const float* Wc = (const float*)d_in[2];
    const float* bc = (const float*)d_in[3];
    const float* W1 = (const float*)d_in[4];
    const float* b1 = (const float*)d_in[5];
    const float* W2 = (const float*)d_in[6];
    const float* b2 = (const float*)d_in[7];
    const float* Wa = (const float*)d_in[8];
    const float* ba = (const float*)d_in[9];
    const float* Wr = (const float*)d_in[10];
    const float* br = (const float*)d_in[11];
    const float* Ww = (const float*)d_in[12];
    const float* bw = (const float*)d_in[13];
    float* out = (float*)d_out;

    cudaFuncSetAttribute(gemm_kernel, cudaFuncAttributeMaxDynamicSharedMemorySize, GEMM_SMEM);
    cudaFuncSetAttribute(mlp_kernel,  cudaFuncAttributeMaxDynamicSharedMemorySize,
                         (128 + 256) * SPAD * 4);

    gemm_kernel<<<GRID_GEMM, 256, GEMM_SMEM>>>(features, Wc);
    gather_pool_kernel<<<BN, 128>>>(vertices, bc);
    mlp_kernel<<<BN / MBV, 256, (128 + 256) * SPAD * 4>>>(W1, b1, W2, b2, Wa, ba, Wr, br, Ww, bw, out);
}

// round 10
// speedup vs baseline: 3.3539x; 1.1359x over previous
#include <cuda_runtime.h>
#include <cstdint>

#define W_  256
#define H_  256
#define C_  256
#define HW_ 65536
#define B_  4
#define BN  4096
#define OC  128
#define NT  256
#define NTILES 1024            // B_*HW_/NT
#define GRID_GEMM 148
#define AFRAG_BYTES 131072
#define CHUNK_BYTES 32768      // 32k x 256hw x 4B
#define GEMM_SMEM (AFRAG_BYTES + 3*CHUNK_BYTES)   // 229376

__device__ float g_G[(size_t)B_ * HW_ * OC];   // [b][hw][o]
__device__ float g_pooled[BN * OC];

__device__ __forceinline__ uint32_t f2tf(float x) {
    uint32_t r; asm("cvt.rna.tf32.f32 %0, %1;" : "=r"(r) : "f"(x)); return r;
}
__device__ __forceinline__ uint32_t s2u(const void* p) {
    uint32_t a;
    asm("{ .reg .u64 t; cvta.to.shared.u64 t, %1; cvt.u32.u64 %0, t; }" : "=r"(a) : "l"(p));
    return a;
}
__device__ __forceinline__ void mma8(float* d, uint4 a, uint32_t b0, uint32_t b1) {
    asm volatile("mma.sync.aligned.m16n8k8.row.col.f32.tf32.tf32.f32 "
        "{%0,%1,%2,%3}, {%4,%5,%6,%7}, {%8,%9}, {%0,%1,%2,%3};"
        : "+f"(d[0]), "+f"(d[1]), "+f"(d[2]), "+f"(d[3])
        : "r"(a.x), "r"(a.y), "r"(a.z), "r"(a.w), "r"(b0), "r"(b1));
}

// issue one k32 x hw256 feature chunk via cp.async (XOR-swizzled), commit group.
// 512 threads: thread -> (row = tid>>4, 4x16B segments of 64 floats at (tid&15)*16)
__device__ __forceinline__ void issue_chunk(const float* __restrict__ f,
                                            int t, int c, uint32_t dst_base, int tid)
{
    if (t < NTILES) {
        const int b = t >> 8, hw0 = (t & 255) * NT;
        const int row = tid >> 4;
        const int col0 = (tid & 15) * 16;
        const float* src = f + ((size_t)(b * C_ + c * 32 + row)) * HW_ + hw0 + col0;
        #pragma unroll
        for (int j = 0; j < 4; j++) {
            const int col  = col0 + j * 4;
            const int colp = col ^ ((row & 3) << 3);
            const uint32_t dst = dst_base + ((uint32_t)(row * 256 + colp)) * 4u;
            asm volatile("cp.async.cg.shared.global [%0], [%1], 16;"
                         :: "r"(dst), "l"(src + j * 4) : "memory");
        }
    }
    asm volatile("cp.async.commit_group;" ::: "memory");
}

// ============================================================================
// GEMM: G[b][hw][o] = sum_c Wc[o][c]*F[b][c][hw].  tf32 mma.sync.
// 512 threads (16 warps). CTA tile m128 x n256, warp tile m32 x n64.
// B streamed raw via cp.async; rounded rna->tf32 at the LDS->mma boundary.
// ============================================================================
__global__ __launch_bounds__(512, 1)
void gemm_kernel(const float* __restrict__ features, const float* __restrict__ Wc)
{
    extern __shared__ __align__(16) char dsm[];
    const uint32_t bs_u = s2u(dsm) + AFRAG_BYTES;

    const int tid = threadIdx.x, wid = tid >> 5, lane = tid & 31;
    const int g = lane >> 2, t4 = lane & 3;
    const int mg = wid & 3, ng = wid >> 2;        // m-group (o 32), n-group (hw 64)

    // start streaming chunks 0..2 immediately (hide DRAM under A build)
    int tn = blockIdx.x, cn = 0;
    #pragma unroll
    for (int i = 0; i < 3; i++) {
        issue_chunk(features, tn, cn, bs_u + i * CHUNK_BYTES, tid);
        if (++cn == 8) { cn = 0; tn += GRID_GEMM; }
    }

    // A fragments: warps 0..7; warp w builds m16 strip w (o = 16w..16w+15)
    if (wid < 8) {
        const int o0 = wid * 16;
        for (int k = 0; k < 32; k++) {
            uint4 a;
            a.x = f2tf(__ldg(&Wc[(o0 + g    ) * 256 + k * 8 + t4    ]));
            a.y = f2tf(__ldg(&Wc[(o0 + g + 8) * 256 + k * 8 + t4    ]));
            a.z = f2tf(__ldg(&Wc[(o0 + g    ) * 256 + k * 8 + t4 + 4]));
            a.w = f2tf(__ldg(&Wc[(o0 + g + 8) * 256 + k * 8 + t4 + 4]));
            *(uint4*)(dsm + (((k * 8 + wid) * 32) + lane) * 16) = a;
        }
    }

    int bufi = 0;
    for (int t = blockIdx.x; t < NTILES; t += GRID_GEMM) {
        float acc[2][8][4];
        #pragma unroll
        for (int mi = 0; mi < 2; mi++)
            #pragma unroll
            for (int ni = 0; ni < 8; ni++)
                #pragma unroll
                for (int q = 0; q < 4; q++) acc[mi][ni][q] = 0.f;

        #pragma unroll
        for (int c = 0; c < 8; c++) {
            asm volatile("cp.async.wait_group 2;" ::: "memory");
            __syncthreads();                       // chunk ready (and A frags on c==0)
            const float* bb = (const float*)(dsm + AFRAG_BYTES + bufi * CHUNK_BYTES);
            #pragma unroll
            for (int kkl = 0; kkl < 4; kkl++) {
                const int ka = c * 4 + kkl;
                uint4 a[2];
                #pragma unroll
                for (int mi = 0; mi < 2; mi++)
                    a[mi] = *(const uint4*)(dsm + ((ka * 8 + mg * 2 + mi) * 32 + lane) * 16);
                #pragma unroll
                for (int ni = 0; ni < 8; ni++) {
                    const int colp = (ng * 64 + ni * 8 + g) ^ (t4 << 3);
                    // round-to-nearest tf32 (raw bits would truncate -> biased)
                    const uint32_t b0 = f2tf(bb[(kkl * 8 + t4    ) * 256 + colp]);
                    const uint32_t b1 = f2tf(bb[(kkl * 8 + t4 + 4) * 256 + colp]);
                    #pragma unroll
                    for (int mi = 0; mi < 2; mi++) mma8(acc[mi][ni], a[mi], b0, b1);
                }
            }
            __syncthreads();                       // done reading this buffer
            issue_chunk(features, tn, cn, bs_u + bufi * CHUNK_BYTES, tid);
            if (++cn == 8) { cn = 0; tn += GRID_GEMM; }
            bufi = (bufi == 2) ? 0 : bufi + 1;
        }
        // epilogue: D -> g_G[b][hw][o]
        {
            const int b = t >> 8, hw0 = (t & 255) * NT;
            float* gb = g_G + (size_t)b * HW_ * OC;
            #pragma unroll
            for (int mi = 0; mi < 2; mi++)
                #pragma unroll
                for (int ni = 0; ni < 8; ni++) {
                    const int o  = mg * 32 + mi * 16 + g;
                    const int hw = hw0 + ng * 64 + ni * 8 + 2 * t4;
                    float* p = gb + (size_t)hw * OC + o;
                    p[0]      = acc[mi][ni][0];
                    p[OC]     = acc[mi][ni][1];
                    p[8]      = acc[mi][ni][2];
                    p[OC + 8] = acc[mi][ni][3];
                }
        }
    }
}

// ============================================================================
// Gather: bilinear on G + bias + relu + 7x7 mean. Block = vertex, thread = o.
// ============================================================================
__global__ __launch_bounds__(128)
void gather_pool_kernel(const float* __restrict__ vertices, const float* __restrict__ bc)
{
    const int bid = blockIdx.x, o = threadIdx.x, b = bid >> 10;
    const float fx = vertices[bid * 2] - 3.5f, fy = vertices[bid * 2 + 1] - 3.5f;
    int ix = (int)floorf(fx), iy = (int)floorf(fy);
    const float lx = fx - ix, ly = fy - iy;
    ix = max(0, min(ix, W_ - 8)); iy = max(0, min(iy, H_ - 8));
    const float hx = 1.f - lx, hy = 1.f - ly;
    const float w00 = hy * hx, w01 = hy * lx, w10 = ly * hx, w11 = ly * lx;
    const float bias = __ldg(&bc[o]);

    const float* base = g_G + ((size_t)b * HW_ + (size_t)iy * W_ + ix) * OC + o;
    float prev[8], cur[8], acc = 0.f;
    #pragma unroll
    for (int r = 0; r < 8; r++) {
        #pragma unroll
        for (int c = 0; c < 8; c++) cur[c] = __ldg(base + ((size_t)r * W_ + c) * OC);
        if (r > 0) {
            #pragma unroll
            for (int px = 0; px < 7; px++) {
                const float v = w00 * prev[px] + w01 * prev[px + 1]
                              + w10 * cur[px]  + w11 * cur[px + 1] + bias;
                acc += fmaxf(v, 0.f);
            }
        }
        #pragma unroll
        for (int c = 0; c < 8; c++) prev[c] = cur[c];
    }
    g_pooled[bid * OC + o] = acc * (1.0f / 49.0f);
}

// ============================================================================
// MLP + heads. 32 vertices/block (128 blocks), 256 threads.
// ============================================================================
#define MBV 32
#define SPAD 36
__global__ __launch_bounds__(256)
void mlp_kernel(const float* __restrict__ W1, const float* __restrict__ b1,
                const float* __restrict__ W2, const float* __restrict__ b2,
                const float* __restrict__ Wa, const float* __restrict__ ba,
                const float* __restrict__ Wr, const float* __restrict__ br,
                const float* __restrict__ Ww, const float* __restrict__ bw,
                float* __restrict__ out)
{
    extern __shared__ __align__(16) float ms[];
    float* sP = ms;                 // [128][SPAD] pooled (k-major), later h2T
    float* sH = ms + 128 * SPAD;    // [256][SPAD] h1T

    const int tid = threadIdx.x, base = blockIdx.x * MBV;

    for (int e = tid; e < MBV * 128; e += 256) {
        const int v = e >> 7, k = e & 127;
        sP[k * SPAD + v] = g_pooled[(base + v) * 128 + k];
    }
    __syncthreads();

    // ---- h1: thread = (oq 64, vq 4): outputs oq*4..+3, vertices vq*8..+7 ----
    {
        const int oq = tid >> 2, vq = tid & 3;
        float acc[4][8];
        #pragma unroll
        for (int r = 0; r < 4; r++)
            #pragma unroll
            for (int j = 0; j < 8; j++) acc[r][j] = 0.f;
        #pragma unroll 2
        for (int k4 = 0; k4 < 32; ++k4) {
            float4 wv[4];
            #pragma unroll
            for (int r = 0; r < 4; r++)
                wv[r] = __ldg((const float4*)(W1 + (oq * 4 + r) * 128 + k4 * 4));
            #pragma unroll
            for (int u = 0; u < 4; ++u) {
                const int k = k4 * 4 + u;
                const float4 va = *(const float4*)&sP[k * SPAD + vq * 8];
                const float4 vb = *(const float4*)&sP[k * SPAD + vq * 8 + 4];
                #pragma unroll
                for (int r = 0; r < 4; r++) {
                    const float w = (u == 0) ? wv[r].x : (u == 1) ? wv[r].y
                                  : (u == 2) ? wv[r].z : wv[r].w;
                    acc[r][0] += w * va.x; acc[r][1] += w * va.y;
                    acc[r][2] += w * va.z; acc[r][3] += w * va.w;
                    acc[r][4] += w * vb.x; acc[r][5] += w * vb.y;
                    acc[r][6] += w * vb.z; acc[r][7] += w * vb.w;
                }
            }
        }
        #pragma unroll
        for (int r = 0; r < 4; r++) {
            const int o = oq * 4 + r;
            const float bb = __ldg(&b1[o]);
            float4 r0, r1;
            r0.x = fmaxf(acc[r][0] + bb, 0.f); r0.y = fmaxf(acc[r][1] + bb, 0.f);
            r0.z = fmaxf(acc[r][2] + bb, 0.f); r0.w = fmaxf(acc[r][3] + bb, 0.f);
            r1.x = fmaxf(acc[r][4] + bb, 0.f); r1.y = fmaxf(acc[r][5] + bb, 0.f);
            r1.z = fmaxf(acc[r][6] + bb, 0.f); r1.w = fmaxf(acc[r][7] + bb, 0.f);
            *(float4*)&sH[o * SPAD + vq * 8]     = r0;
            *(float4*)&sH[o * SPAD + vq * 8 + 4] = r1;
        }
    }
    __syncthreads();

    // ---- h2: thread = (oq2 32, vq2 8): outputs oq2*4..+3, vertices vq2*4..+3 ----
    {
        const int oq2 = tid >> 3, vq2 = tid & 7;
        float acc2[4][4];
        #pragma unroll
        for (int r = 0; r < 4; r++)
            #pragma unroll
            for (int j = 0; j < 4; j++) acc2[r][j] = 0.f;
        #pragma unroll 2
        for (int k4 = 0; k4 < 64; ++k4) {
            float4 wv[4];
            #pragma unroll
            for (int r = 0; r < 4; r++)
                wv[r] = __ldg((const float4*)(W2 + (oq2 * 4 + r) * 256 + k4 * 4));
            #pragma unroll
            for (int u = 0; u < 4; ++u) {
                const int k = k4 * 4 + u;
                const float4 va = *(const float4*)&sH[k * SPAD + vq2 * 4];
                #pragma unroll
                for (int r = 0; r < 4; r++) {
                    const float w = (u == 0) ? wv[r].x : (u == 1) ? wv[r].y
                                  : (u == 2) ? wv[r].z : wv[r].w;
                    acc2[r][0] += w * va.x; acc2[r][1] += w * va.y;
                    acc2[r][2] += w * va.z; acc2[r][3] += w * va.w;
                }
            }
        }
        __syncthreads();   // all h1 reads of sP done; reuse sP as h2T
        #pragma unroll
        for (int r = 0; r < 4; r++) {
            const int o = oq2 * 4 + r;
            const float bb = __ldg(&b2[o]);
            float4 rr;
            rr.x = fmaxf(acc2[r][0] + bb, 0.f); rr.y = fmaxf(acc2[r][1] + bb, 0.f);
            rr.z = fmaxf(acc2[r][2] + bb, 0.f); rr.w = fmaxf(acc2[r][3] + bb, 0.f);
            *(float4*)&sP[o * SPAD + vq2 * 4] = rr;
        }
    }
    __syncthreads();

    // ---- heads ----
    if (tid < MBV * 4) {
        const int v = tid >> 2, hd = tid & 3;
        const float* wr; float bias;
        if      (hd == 0) { wr = Wa;       bias = __ldg(&ba[0]); }
        else if (hd == 1) { wr = Wa + 128; bias = __ldg(&ba[1]); }
        else if (hd == 2) { wr = Wr;       bias = __ldg(&br[0]); }
        else              { wr = Ww;       bias = __ldg(&bw[0]); }
        float s = bias;
        #pragma unroll 4
        for (int k = 0; k < 128; k++) s = fmaf(__ldg(&wr[k]), sP[k * SPAD + v], s);
        const int gidx = base + v;
        if      (hd <  2) out[gidx * 2 + hd] = s;
        else if (hd == 2) out[2 * BN + gidx] = s;
        else              out[3 * BN + gidx] = s;
    }
}

// ============================================================================
extern "C" void kernel_launch(void* const* d_in, const int* in_sizes, int n_in,
                              void* d_out, int out_size)
{
    const float* features = (const float*)d_in[0];
    const float* vertices = (const float*)d_in[1];
    const float* Wc = (const float*)d_in[2];
    const float* bc = (const float*)d_in[3];
    const float* W1 = (const float*)d_in[4];
    const float* b1 = (const float*)d_in[5];
    const float* W2 = (const float*)d_in[6];
    const float* b2 = (const float*)d_in[7];
    const float* Wa = (const float*)d_in[8];
    const float* ba = (const float*)d_in[9];
    const float* Wr = (const float*)d_in[10];
    const float* br = (const float*)d_in[11];
    const float* Ww = (const float*)d_in[12];
    const float* bw = (const float*)d_in[13];
    float* out = (float*)d_out;

    cudaFuncSetAttribute(gemm_kernel, cudaFuncAttributeMaxDynamicSharedMemorySize, GEMM_SMEM);
    cudaFuncSetAttribute(mlp_kernel,  cudaFuncAttributeMaxDynamicSharedMemorySize,
                         (128 + 256) * SPAD * 4);

    gemm_kernel<<<GRID_GEMM, 512, GEMM_SMEM>>>(features, Wc);
    gather_pool_kernel<<<BN, 128>>>(vertices, bc);
    mlp_kernel<<<BN / MBV, 256, (128 + 256) * SPAD * 4>>>(W1, b1, W2, b2, Wa, ba, Wr, br, Ww, bw, out);
}